// round 1
// baseline (speedup 1.0000x reference)
#include <cuda_runtime.h>
#include <cuda_bf16.h>
#include <cstdint>

#define BB 4
#define TT 1024
#define CC 1024
#define HH 16
#define HD 64
#define FF 4096
#define VV 32000
#define NLAYER 4

// ---------------- scratch (device globals: allocation-free rule) ----------------
__device__ float g_x[BB * TT * CC];       // activations (B*T, C)
__device__ float g_q[BB * TT * CC];
__device__ float g_k[BB * TT * CC];
__device__ float g_v[BB * TT * CC];
__device__ float g_o[BB * TT * CC];       // attention output
__device__ float g_ffn[BB * TT * FF];     // FFN hidden
__device__ float g_att[(size_t)BB * HH * TT * TT];  // scores (256 MB)

// ---------------- embedding ----------------
__global__ void embed_kernel(const int* __restrict__ idx,
                             const float* __restrict__ tok,
                             const float* __restrict__ pos,
                             float* __restrict__ x) {
    int t = blockIdx.x;              // 0..B*T-1
    int tpos = t & (TT - 1);
    int id = idx[t];
    const float4* te = (const float4*)(tok + (size_t)id * CC);
    const float4* pe = (const float4*)(pos + (size_t)tpos * CC);
    float4* xo = (float4*)(x + (size_t)t * CC);
    int c = threadIdx.x;             // 256 threads, CC/4 = 256 float4
    float4 a = te[c], b = pe[c];
    xo[c] = make_float4(a.x + b.x, a.y + b.y, a.z + b.z, a.w + b.w);
}

// ---------------- SGEMM: C(MxN) = A(MxK) @ B, row-major ----------------
// TRANSB=0: B is (K x N) row-major.  TRANSB=1: B is (N x K) row-major (C = A @ B^T).
// EPI: 0 = store, 1 = C += AB (read-modify-write), 2 = relu(AB)
// Requires: M%128==0, N%128==0, K%8==0.
#define GM 128
#define GN 128
#define GK 8

template <int TRANSB, int EPI>
__global__ __launch_bounds__(256)
void sgemm_kernel(const float* __restrict__ A, const float* __restrict__ B,
                  float* __restrict__ C, int M, int N, int K) {
    __shared__ float As[GK][GM + 4];
    __shared__ float Bs[GK][GN + 4];

    int tid = threadIdx.x;
    int tx = tid & 15;        // 0..15 -> N
    int ty = tid >> 4;        // 0..15 -> M
    int bx = blockIdx.x;      // N tile
    int by = blockIdx.y;      // M tile

    const float* Ab = A + (size_t)by * GM * K;

    // load indices
    int a_row = tid >> 1;             // 0..127
    int a_col = (tid & 1) << 2;       // 0 or 4
    int bn_row = tid >> 5;            // 0..7   (k), NN
    int bn_col = (tid & 31) << 2;     // 0..124 (n), NN
    int bt_row = tid >> 1;            // 0..127 (n), NT
    int bt_col = (tid & 1) << 2;      // 0 or 4 (k), NT

    float acc[8][8];
#pragma unroll
    for (int i = 0; i < 8; i++)
#pragma unroll
        for (int j = 0; j < 8; j++) acc[i][j] = 0.f;

    for (int k0 = 0; k0 < K; k0 += GK) {
        float4 av = *(const float4*)(Ab + (size_t)a_row * K + k0 + a_col);
        As[a_col + 0][a_row] = av.x;
        As[a_col + 1][a_row] = av.y;
        As[a_col + 2][a_row] = av.z;
        As[a_col + 3][a_row] = av.w;
        if (TRANSB) {
            float4 bv = *(const float4*)(B + (size_t)(bx * GN + bt_row) * K + k0 + bt_col);
            Bs[bt_col + 0][bt_row] = bv.x;
            Bs[bt_col + 1][bt_row] = bv.y;
            Bs[bt_col + 2][bt_row] = bv.z;
            Bs[bt_col + 3][bt_row] = bv.w;
        } else {
            float4 bv = *(const float4*)(B + (size_t)(k0 + bn_row) * N + bx * GN + bn_col);
            *(float4*)&Bs[bn_row][bn_col] = bv;
        }
        __syncthreads();

#pragma unroll
        for (int k = 0; k < GK; k++) {
            float4 a0 = *(const float4*)&As[k][ty * 8];
            float4 a1 = *(const float4*)&As[k][ty * 8 + 4];
            float4 b0 = *(const float4*)&Bs[k][tx * 8];
            float4 b1 = *(const float4*)&Bs[k][tx * 8 + 4];
            float ar[8] = {a0.x, a0.y, a0.z, a0.w, a1.x, a1.y, a1.z, a1.w};
            float br[8] = {b0.x, b0.y, b0.z, b0.w, b1.x, b1.y, b1.z, b1.w};
#pragma unroll
            for (int i = 0; i < 8; i++)
#pragma unroll
                for (int j = 0; j < 8; j++) acc[i][j] += ar[i] * br[j];
        }
        __syncthreads();
    }

    int row0 = by * GM + ty * 8;
    int col0 = bx * GN + tx * 8;
#pragma unroll
    for (int i = 0; i < 8; i++) {
        float* p = C + (size_t)(row0 + i) * N + col0;
        float4 v0 = make_float4(acc[i][0], acc[i][1], acc[i][2], acc[i][3]);
        float4 v1 = make_float4(acc[i][4], acc[i][5], acc[i][6], acc[i][7]);
        if (EPI == 1) {
            float4 c0 = *(const float4*)p;
            float4 c1 = *(const float4*)(p + 4);
            v0.x += c0.x; v0.y += c0.y; v0.z += c0.z; v0.w += c0.w;
            v1.x += c1.x; v1.y += c1.y; v1.z += c1.z; v1.w += c1.w;
        }
        if (EPI == 2) {
            v0.x = fmaxf(v0.x, 0.f); v0.y = fmaxf(v0.y, 0.f);
            v0.z = fmaxf(v0.z, 0.f); v0.w = fmaxf(v0.w, 0.f);
            v1.x = fmaxf(v1.x, 0.f); v1.y = fmaxf(v1.y, 0.f);
            v1.z = fmaxf(v1.z, 0.f); v1.w = fmaxf(v1.w, 0.f);
        }
        *(float4*)p = v0;
        *(float4*)(p + 4) = v1;
    }
}

// ---------------- attention: scores  att[z,i,j] = 0.125 * q[i,:]·k[j,:] ----------------
// grid (tj=16, ti=16, z=64), block 256. Only lower-triangular tiles are computed.
__global__ __launch_bounds__(256)
void attn_score_kernel(const float* __restrict__ q, const float* __restrict__ k,
                       float* __restrict__ att) {
    int tj = blockIdx.x, ti = blockIdx.y;
    if (tj > ti) return;
    int z = blockIdx.z;
    int b = z >> 4, h = z & 15;

    __shared__ float Qt[64][68];   // Qt[d][i]
    __shared__ float Kt[64][68];   // Kt[d][j]

    const float* qb = q + ((size_t)b * TT + ti * 64) * CC + h * HD;
    const float* kb = k + ((size_t)b * TT + tj * 64) * CC + h * HD;
    int tid = threadIdx.x;

#pragma unroll
    for (int l = 0; l < 4; l++) {
        int idx4 = tid + l * 256;          // 0..1023
        int r = idx4 >> 4;                 // 0..63
        int c4 = (idx4 & 15) << 2;         // 0..60
        float4 a = *(const float4*)(qb + (size_t)r * CC + c4);
        Qt[c4 + 0][r] = a.x; Qt[c4 + 1][r] = a.y; Qt[c4 + 2][r] = a.z; Qt[c4 + 3][r] = a.w;
        float4 w = *(const float4*)(kb + (size_t)r * CC + c4);
        Kt[c4 + 0][r] = w.x; Kt[c4 + 1][r] = w.y; Kt[c4 + 2][r] = w.z; Kt[c4 + 3][r] = w.w;
    }
    __syncthreads();

    int tx = tid & 15, ty = tid >> 4;
    float acc[4][4];
#pragma unroll
    for (int i = 0; i < 4; i++)
#pragma unroll
        for (int j = 0; j < 4; j++) acc[i][j] = 0.f;

#pragma unroll 8
    for (int d = 0; d < 64; d++) {
        float4 a4 = *(const float4*)&Qt[d][ty * 4];
        float4 b4 = *(const float4*)&Kt[d][tx * 4];
        float ar[4] = {a4.x, a4.y, a4.z, a4.w};
        float br[4] = {b4.x, b4.y, b4.z, b4.w};
#pragma unroll
        for (int i = 0; i < 4; i++)
#pragma unroll
            for (int j = 0; j < 4; j++) acc[i][j] += ar[i] * br[j];
    }

    float* ab = att + (size_t)z * TT * TT + (size_t)(ti * 64) * TT + tj * 64;
#pragma unroll
    for (int i = 0; i < 4; i++) {
        float4 v = make_float4(acc[i][0] * 0.125f, acc[i][1] * 0.125f,
                               acc[i][2] * 0.125f, acc[i][3] * 0.125f);
        *(float4*)(ab + (size_t)(ty * 4 + i) * TT + tx * 4) = v;
    }
}

// ---------------- softmax over causal prefix; zero-fill to 64-tile boundary ----------------
__global__ __launch_bounds__(128)
void softmax_kernel(float* __restrict__ att) {
    int gid = blockIdx.x;                // z*T + i
    int i = gid & (TT - 1);
    int z = gid >> 10;
    float* row = att + (size_t)z * TT * TT + (size_t)i * TT;
    int len = i + 1;
    int tid = threadIdx.x;

    __shared__ float red[128];

    float m = -1e30f;
    for (int j = tid; j < len; j += 128) m = fmaxf(m, row[j]);
    red[tid] = m; __syncthreads();
    for (int s = 64; s > 0; s >>= 1) {
        if (tid < s) red[tid] = fmaxf(red[tid], red[tid + s]);
        __syncthreads();
    }
    m = red[0]; __syncthreads();

    float sum = 0.f;
    for (int j = tid; j < len; j += 128) {
        float e = __expf(row[j] - m);
        row[j] = e;
        sum += e;
    }
    red[tid] = sum; __syncthreads();
    for (int s = 64; s > 0; s >>= 1) {
        if (tid < s) red[tid] += red[tid + s];
        __syncthreads();
    }
    float inv = 1.f / red[0];

    for (int j = tid; j < len; j += 128) row[j] *= inv;

    int tile_end = ((i >> 6) + 1) << 6;
    for (int j = len + tid; j < tile_end; j += 128) row[j] = 0.f;
}

// ---------------- AV: o[b, i, h*64+d] = sum_{j tiles <= ti} att[z,i,j] * v[b,j,h*64+d] ----------------
// grid (ti=16, z=64), block 256
__global__ __launch_bounds__(256)
void attn_av_kernel(const float* __restrict__ att, const float* __restrict__ v,
                    float* __restrict__ o) {
    int ti = blockIdx.x;
    int z = blockIdx.y;
    int b = z >> 4, h = z & 15;

    __shared__ float Ast[64][68];  // Ast[j][i]
    __shared__ float Vs[64][64];   // Vs[j][d]

    int tid = threadIdx.x;
    int tx = tid & 15, ty = tid >> 4;
    float acc[4][4];
#pragma unroll
    for (int i = 0; i < 4; i++)
#pragma unroll
        for (int j = 0; j < 4; j++) acc[i][j] = 0.f;

    const float* attb = att + (size_t)z * TT * TT + (size_t)(ti * 64) * TT;
    const float* vb = v + (size_t)b * TT * CC + h * HD;

    for (int tj = 0; tj <= ti; ++tj) {
#pragma unroll
        for (int l = 0; l < 4; l++) {
            int idx4 = tid + l * 256;
            int r = idx4 >> 4;             // 0..63
            int c4 = (idx4 & 15) << 2;     // 0..60
            float4 a = *(const float4*)(attb + (size_t)r * TT + tj * 64 + c4);
            Ast[c4 + 0][r] = a.x; Ast[c4 + 1][r] = a.y;
            Ast[c4 + 2][r] = a.z; Ast[c4 + 3][r] = a.w;
            float4 vv = *(const float4*)(vb + (size_t)(tj * 64 + r) * CC + c4);
            *(float4*)&Vs[r][c4] = vv;
        }
        __syncthreads();

#pragma unroll 8
        for (int j = 0; j < 64; j++) {
            float4 a4 = *(const float4*)&Ast[j][ty * 4];
            float4 v4 = *(const float4*)&Vs[j][tx * 4];
            float ar[4] = {a4.x, a4.y, a4.z, a4.w};
            float vr[4] = {v4.x, v4.y, v4.z, v4.w};
#pragma unroll
            for (int i = 0; i < 4; i++)
#pragma unroll
                for (int d = 0; d < 4; d++) acc[i][d] += ar[i] * vr[d];
        }
        __syncthreads();
    }

    float* ob = o + ((size_t)b * TT + ti * 64) * CC + h * HD;
#pragma unroll
    for (int i = 0; i < 4; i++) {
        float4 r0 = make_float4(acc[i][0], acc[i][1], acc[i][2], acc[i][3]);
        *(float4*)(ob + (size_t)(ty * 4 + i) * CC + tx * 4) = r0;
    }
}

// ---------------- launch ----------------
extern "C" void kernel_launch(void* const* d_in, const int* in_sizes, int n_in,
                              void* d_out, int out_size) {
    const int*   idx    = (const int*)d_in[0];
    const float* tok    = (const float*)d_in[1];
    const float* pos    = (const float*)d_in[2];
    const float* wk     = (const float*)d_in[3];
    const float* wq     = (const float*)d_in[4];
    const float* wv     = (const float*)d_in[5];
    const float* w_proj = (const float*)d_in[6];
    const float* w_in   = (const float*)d_in[7];
    const float* w_out  = (const float*)d_in[8];
    float* out = (float*)d_out;

    float *x, *q, *k, *v, *o, *ffn, *att;
    cudaGetSymbolAddress((void**)&x,   g_x);
    cudaGetSymbolAddress((void**)&q,   g_q);
    cudaGetSymbolAddress((void**)&k,   g_k);
    cudaGetSymbolAddress((void**)&v,   g_v);
    cudaGetSymbolAddress((void**)&o,   g_o);
    cudaGetSymbolAddress((void**)&ffn, g_ffn);
    cudaGetSymbolAddress((void**)&att, g_att);

    const int M = BB * TT;  // 4096

    embed_kernel<<<M, 256>>>(idx, tok, pos, x);

    for (int layer = 0; layer < NLAYER; ++layer) {
        // reference quirk: k <- wk, v <- wq, q <- wv
        sgemm_kernel<0, 0><<<dim3(CC / GN, M / GM), 256>>>(x, wk, k, M, CC, CC);
        sgemm_kernel<0, 0><<<dim3(CC / GN, M / GM), 256>>>(x, wq, v, M, CC, CC);
        sgemm_kernel<0, 0><<<dim3(CC / GN, M / GM), 256>>>(x, wv, q, M, CC, CC);

        attn_score_kernel<<<dim3(16, 16, BB * HH), 256>>>(q, k, att);
        softmax_kernel<<<BB * HH * TT, 128>>>(att);
        attn_av_kernel<<<dim3(16, BB * HH), 256>>>(att, v, o);

        // x += o @ w_proj^T   (w_proj is (C x C) row-major over (c, n*64+h))
        sgemm_kernel<1, 1><<<dim3(CC / GN, M / GM), 256>>>(o, w_proj, x, M, CC, CC);

        // ffn = relu(x @ w_in);  x += ffn @ w_out
        sgemm_kernel<0, 2><<<dim3(FF / GN, M / GM), 256>>>(x, w_in, ffn, M, FF, CC);
        sgemm_kernel<0, 1><<<dim3(CC / GN, M / GM), 256>>>(ffn, w_out, x, M, CC, FF);
    }

    // logits = x @ token_emb^T
    sgemm_kernel<1, 0><<<dim3(VV / GN, M / GM), 256>>>(x, tok, out, M, VV, CC);
}

// round 3
// speedup vs baseline: 2.3423x; 2.3423x over previous
#include <cuda_runtime.h>
#include <cuda_bf16.h>
#include <cstdint>

#define BB 4
#define TT 1024
#define CC 1024
#define HH 16
#define HD 64
#define FF 4096
#define VV 32000
#define NLAYER 4

// ---------------- scratch (device globals: allocation-free rule) ----------------
__device__ float g_x[BB * TT * CC];
__device__ float g_q[BB * TT * CC];
__device__ float g_k[BB * TT * CC];
__device__ float g_v[BB * TT * CC];
__device__ float g_o[BB * TT * CC];
__device__ float g_ffn[BB * TT * FF];
__device__ float g_att[(size_t)BB * HH * TT * TT];

// split-bf16 operand buffers
__device__ __nv_bfloat16 g_wk_hi[CC * CC], g_wk_lo[CC * CC];
__device__ __nv_bfloat16 g_wq_hi[CC * CC], g_wq_lo[CC * CC];
__device__ __nv_bfloat16 g_wv_hi[CC * CC], g_wv_lo[CC * CC];
__device__ __nv_bfloat16 g_wp_hi[CC * CC], g_wp_lo[CC * CC];
__device__ __nv_bfloat16 g_win_hi[FF * CC], g_win_lo[FF * CC];
__device__ __nv_bfloat16 g_wout_hi[CC * FF], g_wout_lo[CC * FF];
__device__ __nv_bfloat16 g_tok_hi[(size_t)VV * CC], g_tok_lo[(size_t)VV * CC];
__device__ __nv_bfloat16 g_ahi[BB * TT * FF], g_alo[BB * TT * FF];

// ================= PTX helpers (baseline ISA only: sm_80+) =================
__device__ __forceinline__ uint32_t smem_to_u32(const void* p) {
    uint32_t a;
    asm("{ .reg .u64 t; cvta.to.shared.u64 t, %1; cvt.u32.u64 %0, t; }" : "=r"(a) : "l"(p));
    return a;
}
__device__ __forceinline__ void cpasync16(uint32_t dst, const void* src) {
    asm volatile("cp.async.cg.shared.global [%0], [%1], 16;" :: "r"(dst), "l"(src));
}
#define CP_COMMIT() asm volatile("cp.async.commit_group;" ::: "memory")
#define CP_WAIT0()  asm volatile("cp.async.wait_group 0;" ::: "memory")

__device__ __forceinline__ void ldsm4(uint32_t* r, uint32_t addr) {
    asm volatile("ldmatrix.sync.aligned.m8n8.x4.shared.b16 {%0,%1,%2,%3}, [%4];"
                 : "=r"(r[0]), "=r"(r[1]), "=r"(r[2]), "=r"(r[3]) : "r"(addr));
}
__device__ __forceinline__ void mma16816(float* d, const uint32_t* a, uint32_t b0, uint32_t b1) {
    asm volatile(
        "mma.sync.aligned.m16n8k16.row.col.f32.bf16.bf16.f32 "
        "{%0,%1,%2,%3}, {%4,%5,%6,%7}, {%8,%9}, {%0,%1,%2,%3};"
        : "+f"(d[0]), "+f"(d[1]), "+f"(d[2]), "+f"(d[3])
        : "r"(a[0]), "r"(a[1]), "r"(a[2]), "r"(a[3]), "r"(b0), "r"(b1));
}

// ================= split-bf16 HMMA GEMM =================
// D[M,N] = Ahi/lo[M,K] @ (Bhi/lo[N,K])^T, fp32 out. EPI: 0=store,1=C+=D,2=relu
// grid (M/128, N/128), 256 threads. K % 64 == 0.
#define KC 64
#define TILE_BYTES 16384        // 128 rows x 128B (64 bf16)
#define STAGE_BYTES (4 * TILE_BYTES)
#define GEMM_SMEM (2 * STAGE_BYTES)   // 128 KB

__device__ __forceinline__ uint32_t swz(uint32_t off) { return off ^ ((off >> 3) & 0x70); }

__device__ __forceinline__ void load_tile_async(const __nv_bfloat16* __restrict__ src,
                                                size_t row0, int K, int k0,
                                                uint32_t dst_base, int tid) {
#pragma unroll
    for (int l = 0; l < 4; l++) {
        int seg = tid + l * 256;           // 0..1023
        int row = seg >> 3;                // 0..127
        int c16 = seg & 7;                 // 16B column
        uint32_t off = (uint32_t)(row * 128 + c16 * 16);
        cpasync16(dst_base + swz(off), src + (row0 + row) * (size_t)K + k0 + c16 * 8);
    }
}

template <int EPI>
__global__ __launch_bounds__(256, 1)
void mma_gemm(const __nv_bfloat16* __restrict__ Ahi, const __nv_bfloat16* __restrict__ Alo,
              const __nv_bfloat16* __restrict__ Bhi, const __nv_bfloat16* __restrict__ Blo,
              float* __restrict__ C, int M, int N, int K) {
    extern __shared__ __align__(1024) char smem[];
    uint32_t sbase = smem_to_u32(smem);
    int tid = threadIdx.x;
    int wid = tid >> 5, lane = tid & 31;
    int bm = blockIdx.x, bn = blockIdx.y;
    size_t arow0 = (size_t)bm * 128, brow0 = (size_t)bn * 128;

    int wm = wid & 3, wn = wid >> 2;       // 4 x 2 warp grid
    int m0 = wm * 32, n0 = wn * 64;        // warp tile 32 x 64

    float acc[2][8][4];
#pragma unroll
    for (int i = 0; i < 2; i++)
#pragma unroll
        for (int j = 0; j < 8; j++)
#pragma unroll
            for (int r = 0; r < 4; r++) acc[i][j][r] = 0.f;

    const int nch = K / KC;

    // prologue: stage 0 <- chunk 0
    {
        uint32_t st = sbase;
        load_tile_async(Ahi, arow0, K, 0, st, tid);
        load_tile_async(Alo, arow0, K, 0, st + TILE_BYTES, tid);
        load_tile_async(Bhi, brow0, K, 0, st + 2 * TILE_BYTES, tid);
        load_tile_async(Blo, brow0, K, 0, st + 3 * TILE_BYTES, tid);
        CP_COMMIT();
    }

    for (int c = 0; c < nch; ++c) {
        int s = c & 1;
        CP_WAIT0();
        __syncthreads();
        if (c + 1 < nch) {
            uint32_t st = sbase + (s ^ 1) * STAGE_BYTES;
            int k0 = (c + 1) * KC;
            load_tile_async(Ahi, arow0, K, k0, st, tid);
            load_tile_async(Alo, arow0, K, k0, st + TILE_BYTES, tid);
            load_tile_async(Bhi, brow0, K, k0, st + 2 * TILE_BYTES, tid);
            load_tile_async(Blo, brow0, K, k0, st + 3 * TILE_BYTES, tid);
            CP_COMMIT();
        }
        uint32_t stb = sbase + s * STAGE_BYTES;

#pragma unroll
        for (int j = 0; j < 4; j++) {            // 4 k16 steps in chunk
            uint32_t ah[2][4], al[2][4], bh[4][4], bl[4][4];
            int lr = lane & 15, lc = (lane >> 4) * 16;
#pragma unroll
            for (int mt = 0; mt < 2; mt++) {
                uint32_t off = swz((uint32_t)((m0 + mt * 16 + lr) * 128 + j * 32 + lc));
                ldsm4(ah[mt], stb + off);
                ldsm4(al[mt], stb + TILE_BYTES + off);
            }
#pragma unroll
            for (int ng = 0; ng < 4; ng++) {
                uint32_t off = swz((uint32_t)((n0 + ng * 16 + lr) * 128 + j * 32 + lc));
                ldsm4(bh[ng], stb + 2 * TILE_BYTES + off);
                ldsm4(bl[ng], stb + 3 * TILE_BYTES + off);
            }
#pragma unroll
            for (int mt = 0; mt < 2; mt++) {
#pragma unroll
                for (int ng = 0; ng < 4; ng++) {
                    // n8 tile 0 of group: frags {r0, r2}; tile 1: {r1, r3}
                    mma16816(acc[mt][2 * ng],     ah[mt], bh[ng][0], bh[ng][2]);
                    mma16816(acc[mt][2 * ng + 1], ah[mt], bh[ng][1], bh[ng][3]);
                    mma16816(acc[mt][2 * ng],     ah[mt], bl[ng][0], bl[ng][2]);
                    mma16816(acc[mt][2 * ng + 1], ah[mt], bl[ng][1], bl[ng][3]);
                    mma16816(acc[mt][2 * ng],     al[mt], bh[ng][0], bh[ng][2]);
                    mma16816(acc[mt][2 * ng + 1], al[mt], bh[ng][1], bh[ng][3]);
                }
            }
        }
    }

    // epilogue
    int r = lane >> 2, cp = (lane & 3) * 2;
#pragma unroll
    for (int mt = 0; mt < 2; mt++) {
        int grow = bm * 128 + m0 + mt * 16 + r;
#pragma unroll
        for (int t = 0; t < 8; t++) {
            int gcol = bn * 128 + n0 + t * 8 + cp;
            float* p0 = C + (size_t)grow * N + gcol;
            float* p1 = C + (size_t)(grow + 8) * N + gcol;
            float2 v0 = make_float2(acc[mt][t][0], acc[mt][t][1]);
            float2 v1 = make_float2(acc[mt][t][2], acc[mt][t][3]);
            if (EPI == 1) {
                float2 o0 = *(const float2*)p0;
                float2 o1 = *(const float2*)p1;
                v0.x += o0.x; v0.y += o0.y;
                v1.x += o1.x; v1.y += o1.y;
            }
            if (EPI == 2) {
                v0.x = fmaxf(v0.x, 0.f); v0.y = fmaxf(v0.y, 0.f);
                v1.x = fmaxf(v1.x, 0.f); v1.y = fmaxf(v1.y, 0.f);
            }
            *(float2*)p0 = v0;
            *(float2*)p1 = v1;
        }
    }
}

// ================= split / transpose-split conversions =================
__global__ __launch_bounds__(256)
void split_kernel(const float* __restrict__ X, __nv_bfloat16* __restrict__ hi,
                  __nv_bfloat16* __restrict__ lo, int n4) {
    int i = blockIdx.x * 256 + threadIdx.x;
    if (i >= n4) return;
    float4 v = ((const float4*)X)[i];
    __nv_bfloat16 h0 = __float2bfloat16_rn(v.x);
    __nv_bfloat16 h1 = __float2bfloat16_rn(v.y);
    __nv_bfloat16 h2 = __float2bfloat16_rn(v.z);
    __nv_bfloat16 h3 = __float2bfloat16_rn(v.w);
    __nv_bfloat16 l0 = __float2bfloat16_rn(v.x - __bfloat162float(h0));
    __nv_bfloat16 l1 = __float2bfloat16_rn(v.y - __bfloat162float(h1));
    __nv_bfloat16 l2 = __float2bfloat16_rn(v.z - __bfloat162float(h2));
    __nv_bfloat16 l3 = __float2bfloat16_rn(v.w - __bfloat162float(h3));
    ((__nv_bfloat162*)hi)[2 * i]     = __nv_bfloat162(h0, h1);
    ((__nv_bfloat162*)hi)[2 * i + 1] = __nv_bfloat162(h2, h3);
    ((__nv_bfloat162*)lo)[2 * i]     = __nv_bfloat162(l0, l1);
    ((__nv_bfloat162*)lo)[2 * i + 1] = __nv_bfloat162(l2, l3);
}

// W[K][N] fp32 -> T_hi/lo[N][K] bf16. block (32,8), grid (N/32, K/32)
__global__ __launch_bounds__(256)
void tsplit_kernel(const float* __restrict__ W, __nv_bfloat16* __restrict__ Thi,
                   __nv_bfloat16* __restrict__ Tlo, int K, int N) {
    __shared__ float t[32][33];
    int n0 = blockIdx.x * 32, k0 = blockIdx.y * 32;
    int tx = threadIdx.x, ty = threadIdx.y;
#pragma unroll
    for (int r = 0; r < 4; r++)
        t[ty + 8 * r][tx] = W[(size_t)(k0 + ty + 8 * r) * N + n0 + tx];
    __syncthreads();
#pragma unroll
    for (int r = 0; r < 4; r++) {
        float v = t[tx][ty + 8 * r];
        __nv_bfloat16 h = __float2bfloat16_rn(v);
        __nv_bfloat16 l = __float2bfloat16_rn(v - __bfloat162float(h));
        size_t idx = (size_t)(n0 + ty + 8 * r) * K + k0 + tx;
        Thi[idx] = h;
        Tlo[idx] = l;
    }
}

// ---------------- embedding ----------------
__global__ void embed_kernel(const int* __restrict__ idx,
                             const float* __restrict__ tok,
                             const float* __restrict__ pos,
                             float* __restrict__ x) {
    int t = blockIdx.x;
    int tpos = t & (TT - 1);
    int id = idx[t];
    const float4* te = (const float4*)(tok + (size_t)id * CC);
    const float4* pe = (const float4*)(pos + (size_t)tpos * CC);
    float4* xo = (float4*)(x + (size_t)t * CC);
    int c = threadIdx.x;
    float4 a = te[c], b = pe[c];
    xo[c] = make_float4(a.x + b.x, a.y + b.y, a.z + b.z, a.w + b.w);
}

// ---------------- attention (fp32) ----------------
__global__ __launch_bounds__(256)
void attn_score_kernel(const float* __restrict__ q, const float* __restrict__ k,
                       float* __restrict__ att) {
    int tj = blockIdx.x, ti = blockIdx.y;
    if (tj > ti) return;
    int z = blockIdx.z;
    int b = z >> 4, h = z & 15;

    __shared__ float Qt[64][68];
    __shared__ float Kt[64][68];

    const float* qb = q + ((size_t)b * TT + ti * 64) * CC + h * HD;
    const float* kb = k + ((size_t)b * TT + tj * 64) * CC + h * HD;
    int tid = threadIdx.x;

#pragma unroll
    for (int l = 0; l < 4; l++) {
        int idx4 = tid + l * 256;
        int r = idx4 >> 4;
        int c4 = (idx4 & 15) << 2;
        float4 a = *(const float4*)(qb + (size_t)r * CC + c4);
        Qt[c4 + 0][r] = a.x; Qt[c4 + 1][r] = a.y; Qt[c4 + 2][r] = a.z; Qt[c4 + 3][r] = a.w;
        float4 w = *(const float4*)(kb + (size_t)r * CC + c4);
        Kt[c4 + 0][r] = w.x; Kt[c4 + 1][r] = w.y; Kt[c4 + 2][r] = w.z; Kt[c4 + 3][r] = w.w;
    }
    __syncthreads();

    int tx = tid & 15, ty = tid >> 4;
    float acc[4][4];
#pragma unroll
    for (int i = 0; i < 4; i++)
#pragma unroll
        for (int j = 0; j < 4; j++) acc[i][j] = 0.f;

#pragma unroll 8
    for (int d = 0; d < 64; d++) {
        float4 a4 = *(const float4*)&Qt[d][ty * 4];
        float4 b4 = *(const float4*)&Kt[d][tx * 4];
        float ar[4] = {a4.x, a4.y, a4.z, a4.w};
        float br[4] = {b4.x, b4.y, b4.z, b4.w};
#pragma unroll
        for (int i = 0; i < 4; i++)
#pragma unroll
            for (int j = 0; j < 4; j++) acc[i][j] += ar[i] * br[j];
    }

    float* ab = att + (size_t)z * TT * TT + (size_t)(ti * 64) * TT + tj * 64;
#pragma unroll
    for (int i = 0; i < 4; i++) {
        float4 v = make_float4(acc[i][0] * 0.125f, acc[i][1] * 0.125f,
                               acc[i][2] * 0.125f, acc[i][3] * 0.125f);
        *(float4*)(ab + (size_t)(ty * 4 + i) * TT + tx * 4) = v;
    }
}

__global__ __launch_bounds__(128)
void softmax_kernel(float* __restrict__ att) {
    int gid = blockIdx.x;
    int i = gid & (TT - 1);
    int z = gid >> 10;
    float* row = att + (size_t)z * TT * TT + (size_t)i * TT;
    int len = i + 1;
    int tid = threadIdx.x;

    __shared__ float red[128];

    float m = -1e30f;
    for (int j = tid; j < len; j += 128) m = fmaxf(m, row[j]);
    red[tid] = m; __syncthreads();
    for (int s = 64; s > 0; s >>= 1) {
        if (tid < s) red[tid] = fmaxf(red[tid], red[tid + s]);
        __syncthreads();
    }
    m = red[0]; __syncthreads();

    float sum = 0.f;
    for (int j = tid; j < len; j += 128) {
        float e = __expf(row[j] - m);
        row[j] = e;
        sum += e;
    }
    red[tid] = sum; __syncthreads();
    for (int s = 64; s > 0; s >>= 1) {
        if (tid < s) red[tid] += red[tid + s];
        __syncthreads();
    }
    float inv = 1.f / red[0];

    for (int j = tid; j < len; j += 128) row[j] *= inv;

    int tile_end = ((i >> 6) + 1) << 6;
    for (int j = len + tid; j < tile_end; j += 128) row[j] = 0.f;
}

__global__ __launch_bounds__(256)
void attn_av_kernel(const float* __restrict__ att, const float* __restrict__ v,
                    float* __restrict__ o) {
    int ti = blockIdx.x;
    int z = blockIdx.y;
    int b = z >> 4, h = z & 15;

    __shared__ float Ast[64][68];
    __shared__ float Vs[64][64];

    int tid = threadIdx.x;
    int tx = tid & 15, ty = tid >> 4;
    float acc[4][4];
#pragma unroll
    for (int i = 0; i < 4; i++)
#pragma unroll
        for (int j = 0; j < 4; j++) acc[i][j] = 0.f;

    const float* attb = att + (size_t)z * TT * TT + (size_t)(ti * 64) * TT;
    const float* vb = v + (size_t)b * TT * CC + h * HD;

    for (int tj = 0; tj <= ti; ++tj) {
#pragma unroll
        for (int l = 0; l < 4; l++) {
            int idx4 = tid + l * 256;
            int r = idx4 >> 4;
            int c4 = (idx4 & 15) << 2;
            float4 a = *(const float4*)(attb + (size_t)r * TT + tj * 64 + c4);
            Ast[c4 + 0][r] = a.x; Ast[c4 + 1][r] = a.y;
            Ast[c4 + 2][r] = a.z; Ast[c4 + 3][r] = a.w;
            float4 vv = *(const float4*)(vb + (size_t)(tj * 64 + r) * CC + c4);
            *(float4*)&Vs[r][c4] = vv;
        }
        __syncthreads();

#pragma unroll 8
        for (int j = 0; j < 64; j++) {
            float4 a4 = *(const float4*)&Ast[j][ty * 4];
            float4 v4 = *(const float4*)&Vs[j][tx * 4];
            float ar[4] = {a4.x, a4.y, a4.z, a4.w};
            float vr[4] = {v4.x, v4.y, v4.z, v4.w};
#pragma unroll
            for (int i = 0; i < 4; i++)
#pragma unroll
                for (int d = 0; d < 4; d++) acc[i][d] += ar[i] * vr[d];
        }
        __syncthreads();
    }

    float* ob = o + ((size_t)b * TT + ti * 64) * CC + h * HD;
#pragma unroll
    for (int i = 0; i < 4; i++) {
        float4 r0 = make_float4(acc[i][0], acc[i][1], acc[i][2], acc[i][3]);
        *(float4*)(ob + (size_t)(ty * 4 + i) * CC + tx * 4) = r0;
    }
}

// ---------------- launch ----------------
static inline void gemm_launch(int epi, const __nv_bfloat16* ahi, const __nv_bfloat16* alo,
                               const __nv_bfloat16* bhi, const __nv_bfloat16* blo,
                               float* c, int M, int N, int K) {
    dim3 grid(M / 128, N / 128);
    if (epi == 0) mma_gemm<0><<<grid, 256, GEMM_SMEM>>>(ahi, alo, bhi, blo, c, M, N, K);
    if (epi == 1) mma_gemm<1><<<grid, 256, GEMM_SMEM>>>(ahi, alo, bhi, blo, c, M, N, K);
    if (epi == 2) mma_gemm<2><<<grid, 256, GEMM_SMEM>>>(ahi, alo, bhi, blo, c, M, N, K);
}

extern "C" void kernel_launch(void* const* d_in, const int* in_sizes, int n_in,
                              void* d_out, int out_size) {
    const int*   idx    = (const int*)d_in[0];
    const float* tok    = (const float*)d_in[1];
    const float* pos    = (const float*)d_in[2];
    const float* wk     = (const float*)d_in[3];
    const float* wq     = (const float*)d_in[4];
    const float* wv     = (const float*)d_in[5];
    const float* w_proj = (const float*)d_in[6];
    const float* w_in   = (const float*)d_in[7];
    const float* w_out  = (const float*)d_in[8];
    float* out = (float*)d_out;

    static bool attr_done = false;
    if (!attr_done) {
        cudaFuncSetAttribute(mma_gemm<0>, cudaFuncAttributeMaxDynamicSharedMemorySize, GEMM_SMEM);
        cudaFuncSetAttribute(mma_gemm<1>, cudaFuncAttributeMaxDynamicSharedMemorySize, GEMM_SMEM);
        cudaFuncSetAttribute(mma_gemm<2>, cudaFuncAttributeMaxDynamicSharedMemorySize, GEMM_SMEM);
        attr_done = true;
    }

    float *x, *q, *k, *v, *o, *ffn, *att;
    cudaGetSymbolAddress((void**)&x,   g_x);
    cudaGetSymbolAddress((void**)&q,   g_q);
    cudaGetSymbolAddress((void**)&k,   g_k);
    cudaGetSymbolAddress((void**)&v,   g_v);
    cudaGetSymbolAddress((void**)&o,   g_o);
    cudaGetSymbolAddress((void**)&ffn, g_ffn);
    cudaGetSymbolAddress((void**)&att, g_att);

    __nv_bfloat16 *wk_hi, *wk_lo, *wq_hi, *wq_lo, *wv_hi, *wv_lo, *wp_hi, *wp_lo;
    __nv_bfloat16 *win_hi, *win_lo, *wout_hi, *wout_lo, *tok_hi, *tok_lo, *ahi, *alo;
    cudaGetSymbolAddress((void**)&wk_hi, g_wk_hi);   cudaGetSymbolAddress((void**)&wk_lo, g_wk_lo);
    cudaGetSymbolAddress((void**)&wq_hi, g_wq_hi);   cudaGetSymbolAddress((void**)&wq_lo, g_wq_lo);
    cudaGetSymbolAddress((void**)&wv_hi, g_wv_hi);   cudaGetSymbolAddress((void**)&wv_lo, g_wv_lo);
    cudaGetSymbolAddress((void**)&wp_hi, g_wp_hi);   cudaGetSymbolAddress((void**)&wp_lo, g_wp_lo);
    cudaGetSymbolAddress((void**)&win_hi, g_win_hi); cudaGetSymbolAddress((void**)&win_lo, g_win_lo);
    cudaGetSymbolAddress((void**)&wout_hi, g_wout_hi); cudaGetSymbolAddress((void**)&wout_lo, g_wout_lo);
    cudaGetSymbolAddress((void**)&tok_hi, g_tok_hi); cudaGetSymbolAddress((void**)&tok_lo, g_tok_lo);
    cudaGetSymbolAddress((void**)&ahi, g_ahi);       cudaGetSymbolAddress((void**)&alo, g_alo);

    const int M = BB * TT;  // 4096
    dim3 tb(32, 8);

    // ---- per-launch weight conversion ----
    tsplit_kernel<<<dim3(CC / 32, CC / 32), tb>>>(wk, wk_hi, wk_lo, CC, CC);
    tsplit_kernel<<<dim3(CC / 32, CC / 32), tb>>>(wq, wq_hi, wq_lo, CC, CC);
    tsplit_kernel<<<dim3(CC / 32, CC / 32), tb>>>(wv, wv_hi, wv_lo, CC, CC);
    split_kernel<<<(CC * CC / 4 + 255) / 256, 256>>>(w_proj, wp_hi, wp_lo, CC * CC / 4);
    tsplit_kernel<<<dim3(FF / 32, CC / 32), tb>>>(w_in, win_hi, win_lo, CC, FF);
    tsplit_kernel<<<dim3(CC / 32, FF / 32), tb>>>(w_out, wout_hi, wout_lo, FF, CC);
    split_kernel<<<((size_t)VV * CC / 4 + 255) / 256, 256>>>(tok, tok_hi, tok_lo, VV * CC / 4);

    embed_kernel<<<M, 256>>>(idx, tok, pos, x);

    for (int layer = 0; layer < NLAYER; ++layer) {
        // reference quirk: k <- wk, v <- wq, q <- wv
        split_kernel<<<M * CC / 4 / 256, 256>>>(x, ahi, alo, M * CC / 4);
        gemm_launch(0, ahi, alo, wk_hi, wk_lo, k, M, CC, CC);
        gemm_launch(0, ahi, alo, wq_hi, wq_lo, v, M, CC, CC);
        gemm_launch(0, ahi, alo, wv_hi, wv_lo, q, M, CC, CC);

        attn_score_kernel<<<dim3(16, 16, BB * HH), 256>>>(q, k, att);
        softmax_kernel<<<BB * HH * TT, 128>>>(att);
        attn_av_kernel<<<dim3(16, BB * HH), 256>>>(att, v, o);

        // x += o @ w_proj^T
        split_kernel<<<M * CC / 4 / 256, 256>>>(o, ahi, alo, M * CC / 4);
        gemm_launch(1, ahi, alo, wp_hi, wp_lo, x, M, CC, CC);

        // ffn = relu(x @ w_in); x += ffn @ w_out
        split_kernel<<<M * CC / 4 / 256, 256>>>(x, ahi, alo, M * CC / 4);
        gemm_launch(2, ahi, alo, win_hi, win_lo, ffn, M, FF, CC);
        split_kernel<<<M * FF / 4 / 256, 256>>>(ffn, ahi, alo, M * FF / 4);
        gemm_launch(1, ahi, alo, wout_hi, wout_lo, x, M, CC, FF);
    }

    // logits = x @ token_emb^T
    split_kernel<<<M * CC / 4 / 256, 256>>>(x, ahi, alo, M * CC / 4);
    gemm_launch(0, ahi, alo, tok_hi, tok_lo, out, M, VV, CC);
}

// round 4
// speedup vs baseline: 2.4800x; 1.0588x over previous
#include <cuda_runtime.h>
#include <cuda_bf16.h>
#include <cstdint>

#define BB 4
#define TT 1024
#define CC 1024
#define HH 16
#define HD 64
#define FF 4096
#define VV 32000
#define NLAYER 4

// ---------------- scratch (device globals: allocation-free rule) ----------------
__device__ float g_x[BB * TT * CC];
__device__ float g_q[BB * TT * CC];
__device__ float g_k[BB * TT * CC];
__device__ float g_v[BB * TT * CC];

// split activation buffers
__device__ __nv_bfloat16 g_xhi[BB * TT * CC], g_xlo[BB * TT * CC];
__device__ __nv_bfloat16 g_ohi[BB * TT * CC], g_olo[BB * TT * CC];
__device__ __nv_bfloat16 g_hhi[BB * TT * FF], g_hlo[BB * TT * FF];

// split-bf16 weight buffers
__device__ __nv_bfloat16 g_wk_hi[CC * CC], g_wk_lo[CC * CC];
__device__ __nv_bfloat16 g_wq_hi[CC * CC], g_wq_lo[CC * CC];
__device__ __nv_bfloat16 g_wv_hi[CC * CC], g_wv_lo[CC * CC];
__device__ __nv_bfloat16 g_wp_hi[CC * CC], g_wp_lo[CC * CC];
__device__ __nv_bfloat16 g_win_hi[FF * CC], g_win_lo[FF * CC];
__device__ __nv_bfloat16 g_wout_hi[CC * FF], g_wout_lo[CC * FF];
__device__ __nv_bfloat16 g_tok_hi[(size_t)VV * CC], g_tok_lo[(size_t)VV * CC];

// ================= PTX helpers (baseline ISA: sm_80+) =================
__device__ __forceinline__ uint32_t smem_to_u32(const void* p) {
    uint32_t a;
    asm("{ .reg .u64 t; cvta.to.shared.u64 t, %1; cvt.u32.u64 %0, t; }" : "=r"(a) : "l"(p));
    return a;
}
__device__ __forceinline__ void cpasync16(uint32_t dst, const void* src) {
    asm volatile("cp.async.cg.shared.global [%0], [%1], 16;" :: "r"(dst), "l"(src));
}
#define CP_COMMIT() asm volatile("cp.async.commit_group;" ::: "memory")
#define CP_WAIT0()  asm volatile("cp.async.wait_group 0;" ::: "memory")

__device__ __forceinline__ void ldsm4(uint32_t* r, uint32_t addr) {
    asm volatile("ldmatrix.sync.aligned.m8n8.x4.shared.b16 {%0,%1,%2,%3}, [%4];"
                 : "=r"(r[0]), "=r"(r[1]), "=r"(r[2]), "=r"(r[3]) : "r"(addr));
}
__device__ __forceinline__ void mma16816(float* d, const uint32_t* a, uint32_t b0, uint32_t b1) {
    asm volatile(
        "mma.sync.aligned.m16n8k16.row.col.f32.bf16.bf16.f32 "
        "{%0,%1,%2,%3}, {%4,%5,%6,%7}, {%8,%9}, {%0,%1,%2,%3};"
        : "+f"(d[0]), "+f"(d[1]), "+f"(d[2]), "+f"(d[3])
        : "r"(a[0]), "r"(a[1]), "r"(a[2]), "r"(a[3]), "r"(b0), "r"(b1));
}

__device__ __forceinline__ void split_store(__nv_bfloat16* __restrict__ hi,
                                            __nv_bfloat16* __restrict__ lo,
                                            size_t off, float2 v) {
    __nv_bfloat16 h0 = __float2bfloat16_rn(v.x);
    __nv_bfloat16 h1 = __float2bfloat16_rn(v.y);
    __nv_bfloat16 l0 = __float2bfloat16_rn(v.x - __bfloat162float(h0));
    __nv_bfloat16 l1 = __float2bfloat16_rn(v.y - __bfloat162float(h1));
    *(__nv_bfloat162*)(hi + off) = __nv_bfloat162(h0, h1);
    *(__nv_bfloat162*)(lo + off) = __nv_bfloat162(l0, l1);
}

// ================= split-bf16 HMMA GEMM =================
// D[M,N] = Ahi/lo[M,K] @ (Bhi/lo[N,K])^T, fp32 acc.
// EPI 0: C = D
// EPI 1: C += D; split(C) -> Hi/Lo
// EPI 2: split(relu(D)) -> Hi/Lo   (C unused)
#define KC 64
#define TILE_BYTES 16384
#define STAGE_BYTES (4 * TILE_BYTES)
#define GEMM_SMEM (2 * STAGE_BYTES)   // 128 KB

__device__ __forceinline__ uint32_t swz(uint32_t off) { return off ^ ((off >> 3) & 0x70); }

__device__ __forceinline__ void load_tile_async(const __nv_bfloat16* __restrict__ src,
                                                size_t row0, int K, int k0,
                                                uint32_t dst_base, int tid) {
#pragma unroll
    for (int l = 0; l < 4; l++) {
        int seg = tid + l * 256;
        int row = seg >> 3;
        int c16 = seg & 7;
        uint32_t off = (uint32_t)(row * 128 + c16 * 16);
        cpasync16(dst_base + swz(off), src + (row0 + row) * (size_t)K + k0 + c16 * 8);
    }
}

template <int EPI>
__global__ __launch_bounds__(256, 1)
void mma_gemm(const __nv_bfloat16* __restrict__ Ahi, const __nv_bfloat16* __restrict__ Alo,
              const __nv_bfloat16* __restrict__ Bhi, const __nv_bfloat16* __restrict__ Blo,
              float* __restrict__ C, __nv_bfloat16* __restrict__ Hi,
              __nv_bfloat16* __restrict__ Lo, int M, int N, int K) {
    extern __shared__ __align__(1024) char smem[];
    uint32_t sbase = smem_to_u32(smem);
    int tid = threadIdx.x;
    int wid = tid >> 5, lane = tid & 31;
    int bm = blockIdx.x, bn = blockIdx.y;
    size_t arow0 = (size_t)bm * 128, brow0 = (size_t)bn * 128;

    int wm = wid & 3, wn = wid >> 2;
    int m0 = wm * 32, n0 = wn * 64;

    float acc[2][8][4];
#pragma unroll
    for (int i = 0; i < 2; i++)
#pragma unroll
        for (int j = 0; j < 8; j++)
#pragma unroll
            for (int r = 0; r < 4; r++) acc[i][j][r] = 0.f;

    const int nch = K / KC;
    {
        uint32_t st = sbase;
        load_tile_async(Ahi, arow0, K, 0, st, tid);
        load_tile_async(Alo, arow0, K, 0, st + TILE_BYTES, tid);
        load_tile_async(Bhi, brow0, K, 0, st + 2 * TILE_BYTES, tid);
        load_tile_async(Blo, brow0, K, 0, st + 3 * TILE_BYTES, tid);
        CP_COMMIT();
    }

    for (int c = 0; c < nch; ++c) {
        int s = c & 1;
        CP_WAIT0();
        __syncthreads();
        if (c + 1 < nch) {
            uint32_t st = sbase + (s ^ 1) * STAGE_BYTES;
            int k0 = (c + 1) * KC;
            load_tile_async(Ahi, arow0, K, k0, st, tid);
            load_tile_async(Alo, arow0, K, k0, st + TILE_BYTES, tid);
            load_tile_async(Bhi, brow0, K, k0, st + 2 * TILE_BYTES, tid);
            load_tile_async(Blo, brow0, K, k0, st + 3 * TILE_BYTES, tid);
            CP_COMMIT();
        }
        uint32_t stb = sbase + s * STAGE_BYTES;

#pragma unroll
        for (int j = 0; j < 4; j++) {
            uint32_t ah[2][4], al[2][4], bh[4][4], bl[4][4];
            int lr = lane & 15, lc = (lane >> 4) * 16;
#pragma unroll
            for (int mt = 0; mt < 2; mt++) {
                uint32_t off = swz((uint32_t)((m0 + mt * 16 + lr) * 128 + j * 32 + lc));
                ldsm4(ah[mt], stb + off);
                ldsm4(al[mt], stb + TILE_BYTES + off);
            }
#pragma unroll
            for (int ng = 0; ng < 4; ng++) {
                uint32_t off = swz((uint32_t)((n0 + ng * 16 + lr) * 128 + j * 32 + lc));
                ldsm4(bh[ng], stb + 2 * TILE_BYTES + off);
                ldsm4(bl[ng], stb + 3 * TILE_BYTES + off);
            }
#pragma unroll
            for (int mt = 0; mt < 2; mt++) {
#pragma unroll
                for (int ng = 0; ng < 4; ng++) {
                    mma16816(acc[mt][2 * ng],     ah[mt], bh[ng][0], bh[ng][2]);
                    mma16816(acc[mt][2 * ng + 1], ah[mt], bh[ng][1], bh[ng][3]);
                    mma16816(acc[mt][2 * ng],     ah[mt], bl[ng][0], bl[ng][2]);
                    mma16816(acc[mt][2 * ng + 1], ah[mt], bl[ng][1], bl[ng][3]);
                    mma16816(acc[mt][2 * ng],     al[mt], bh[ng][0], bh[ng][2]);
                    mma16816(acc[mt][2 * ng + 1], al[mt], bh[ng][1], bh[ng][3]);
                }
            }
        }
    }

    int r = lane >> 2, cp = (lane & 3) * 2;
#pragma unroll
    for (int mt = 0; mt < 2; mt++) {
        int grow = bm * 128 + m0 + mt * 16 + r;
#pragma unroll
        for (int t = 0; t < 8; t++) {
            int gcol = bn * 128 + n0 + t * 8 + cp;
            size_t o0 = (size_t)grow * N + gcol;
            size_t o1 = (size_t)(grow + 8) * N + gcol;
            float2 v0 = make_float2(acc[mt][t][0], acc[mt][t][1]);
            float2 v1 = make_float2(acc[mt][t][2], acc[mt][t][3]);
            if (EPI == 0) {
                *(float2*)(C + o0) = v0;
                *(float2*)(C + o1) = v1;
            }
            if (EPI == 1) {
                float2 c0 = *(const float2*)(C + o0);
                float2 c1 = *(const float2*)(C + o1);
                v0.x += c0.x; v0.y += c0.y;
                v1.x += c1.x; v1.y += c1.y;
                *(float2*)(C + o0) = v0;
                *(float2*)(C + o1) = v1;
                split_store(Hi, Lo, o0, v0);
                split_store(Hi, Lo, o1, v1);
            }
            if (EPI == 2) {
                v0.x = fmaxf(v0.x, 0.f); v0.y = fmaxf(v0.y, 0.f);
                v1.x = fmaxf(v1.x, 0.f); v1.y = fmaxf(v1.y, 0.f);
                split_store(Hi, Lo, o0, v0);
                split_store(Hi, Lo, o1, v1);
            }
        }
    }
}

// ================= flash attention (fp32, fused) =================
// grid (16, BB*HH); CTA handles q-tile ti = 15 - blockIdx.x of (b,h).
// Writes o directly as split bf16 hi/lo.
#define FA_SMEM (3 * 64 * 68 * 4 + 64 * 64 * 4)

__global__ __launch_bounds__(256)
void flash_attn(const float* __restrict__ q, const float* __restrict__ k,
                const float* __restrict__ v,
                __nv_bfloat16* __restrict__ ohi, __nv_bfloat16* __restrict__ olo) {
    extern __shared__ float fs[];
    float* Qt = fs;                 // [64][68]  (d-major)
    float* Kt = fs + 64 * 68;       // [64][68]  (d-major)
    float* Ps = fs + 2 * 64 * 68;   // [64][68]  (i-major, P[i][j])
    float* Vs = fs + 3 * 64 * 68;   // [64][64]  (j-major, V[j][d])

    int ti = 15 - (int)blockIdx.x;
    int z = blockIdx.y;
    int b = z >> 4, h = z & 15;
    int tid = threadIdx.x, tx = tid & 15, ty = tid >> 4;

    const float* qb = q + ((size_t)b * TT + ti * 64) * CC + h * HD;
#pragma unroll
    for (int l = 0; l < 4; l++) {
        int idx4 = tid + l * 256;
        int r = idx4 >> 4;
        int c4 = (idx4 & 15) << 2;
        float4 a = *(const float4*)(qb + (size_t)r * CC + c4);
        Qt[(c4 + 0) * 68 + r] = a.x; Qt[(c4 + 1) * 68 + r] = a.y;
        Qt[(c4 + 2) * 68 + r] = a.z; Qt[(c4 + 3) * 68 + r] = a.w;
    }
    __syncthreads();

    float m[4], sum[4], o[4][4];
#pragma unroll
    for (int i = 0; i < 4; i++) {
        m[i] = -1e30f; sum[i] = 0.f;
#pragma unroll
        for (int d = 0; d < 4; d++) o[i][d] = 0.f;
    }

    for (int tj = 0; tj <= ti; ++tj) {
        const float* kb = k + ((size_t)b * TT + tj * 64) * CC + h * HD;
        const float* vb = v + ((size_t)b * TT + tj * 64) * CC + h * HD;
#pragma unroll
        for (int l = 0; l < 4; l++) {
            int idx4 = tid + l * 256;
            int r = idx4 >> 4;
            int c4 = (idx4 & 15) << 2;
            float4 w = *(const float4*)(kb + (size_t)r * CC + c4);
            Kt[(c4 + 0) * 68 + r] = w.x; Kt[(c4 + 1) * 68 + r] = w.y;
            Kt[(c4 + 2) * 68 + r] = w.z; Kt[(c4 + 3) * 68 + r] = w.w;
            float4 vv = *(const float4*)(vb + (size_t)r * CC + c4);
            *(float4*)&Vs[r * 64 + c4] = vv;
        }
        __syncthreads();

        float acc[4][4];
#pragma unroll
        for (int i = 0; i < 4; i++)
#pragma unroll
            for (int j = 0; j < 4; j++) acc[i][j] = 0.f;
#pragma unroll 8
        for (int d = 0; d < 64; d++) {
            float4 a4 = *(const float4*)&Qt[d * 68 + ty * 4];
            float4 b4 = *(const float4*)&Kt[d * 68 + tx * 4];
            float ar[4] = {a4.x, a4.y, a4.z, a4.w};
            float br[4] = {b4.x, b4.y, b4.z, b4.w};
#pragma unroll
            for (int i = 0; i < 4; i++)
#pragma unroll
                for (int j = 0; j < 4; j++) acc[i][j] += ar[i] * br[j];
        }
        // scale + causal mask (diagonal tile only)
#pragma unroll
        for (int i = 0; i < 4; i++)
#pragma unroll
            for (int j = 0; j < 4; j++) {
                float s = acc[i][j] * 0.125f;
                if (tj == ti && (tx * 4 + j) > (ty * 4 + i)) s = -1e30f;
                acc[i][j] = s;
            }

        // online softmax per row (rows owned by the 16 lanes sharing ty)
#pragma unroll
        for (int i = 0; i < 4; i++) {
            float tm = fmaxf(fmaxf(acc[i][0], acc[i][1]), fmaxf(acc[i][2], acc[i][3]));
            tm = fmaxf(tm, __shfl_xor_sync(0xffffffffu, tm, 1, 16));
            tm = fmaxf(tm, __shfl_xor_sync(0xffffffffu, tm, 2, 16));
            tm = fmaxf(tm, __shfl_xor_sync(0xffffffffu, tm, 4, 16));
            tm = fmaxf(tm, __shfl_xor_sync(0xffffffffu, tm, 8, 16));
            float mn = fmaxf(m[i], tm);
            float f = __expf(m[i] - mn);
            m[i] = mn;
            float4 p;
            p.x = __expf(acc[i][0] - mn);
            p.y = __expf(acc[i][1] - mn);
            p.z = __expf(acc[i][2] - mn);
            p.w = __expf(acc[i][3] - mn);
            *(float4*)&Ps[(ty * 4 + i) * 68 + tx * 4] = p;
            float ts = p.x + p.y + p.z + p.w;
            ts += __shfl_xor_sync(0xffffffffu, ts, 1, 16);
            ts += __shfl_xor_sync(0xffffffffu, ts, 2, 16);
            ts += __shfl_xor_sync(0xffffffffu, ts, 4, 16);
            ts += __shfl_xor_sync(0xffffffffu, ts, 8, 16);
            sum[i] = sum[i] * f + ts;
#pragma unroll
            for (int d = 0; d < 4; d++) o[i][d] *= f;
        }
        __syncthreads();

        // AV: o[i][d] += P[i][j] * V[j][d]
#pragma unroll 4
        for (int j4 = 0; j4 < 64; j4 += 4) {
            float4 v0 = *(const float4*)&Vs[(j4 + 0) * 64 + tx * 4];
            float4 v1 = *(const float4*)&Vs[(j4 + 1) * 64 + tx * 4];
            float4 v2 = *(const float4*)&Vs[(j4 + 2) * 64 + tx * 4];
            float4 v3 = *(const float4*)&Vs[(j4 + 3) * 64 + tx * 4];
            float vr[4][4] = {{v0.x, v0.y, v0.z, v0.w}, {v1.x, v1.y, v1.z, v1.w},
                              {v2.x, v2.y, v2.z, v2.w}, {v3.x, v3.y, v3.z, v3.w}};
#pragma unroll
            for (int i = 0; i < 4; i++) {
                float4 p = *(const float4*)&Ps[(ty * 4 + i) * 68 + j4];
                float pr[4] = {p.x, p.y, p.z, p.w};
#pragma unroll
                for (int jj = 0; jj < 4; jj++)
#pragma unroll
                    for (int d = 0; d < 4; d++) o[i][d] += pr[jj] * vr[jj][d];
            }
        }
        __syncthreads();
    }

    // write o / sum as split bf16
#pragma unroll
    for (int i = 0; i < 4; i++) {
        float inv = 1.f / sum[i];
        size_t row = (size_t)b * TT + ti * 64 + ty * 4 + i;
        size_t off = row * CC + h * HD + tx * 4;
        split_store(ohi, olo, off,     make_float2(o[i][0] * inv, o[i][1] * inv));
        split_store(ohi, olo, off + 2, make_float2(o[i][2] * inv, o[i][3] * inv));
    }
}

// ================= conversions =================
__global__ __launch_bounds__(256)
void split_kernel(const float* __restrict__ X, __nv_bfloat16* __restrict__ hi,
                  __nv_bfloat16* __restrict__ lo, int n4) {
    int i = blockIdx.x * 256 + threadIdx.x;
    if (i >= n4) return;
    float4 v = ((const float4*)X)[i];
    split_store(hi, lo, (size_t)i * 4,     make_float2(v.x, v.y));
    split_store(hi, lo, (size_t)i * 4 + 2, make_float2(v.z, v.w));
}

// W[K][N] fp32 -> T_hi/lo[N][K] bf16. block (32,8), grid (N/32, K/32)
__global__ __launch_bounds__(256)
void tsplit_kernel(const float* __restrict__ W, __nv_bfloat16* __restrict__ Thi,
                   __nv_bfloat16* __restrict__ Tlo, int K, int N) {
    __shared__ float t[32][33];
    int n0 = blockIdx.x * 32, k0 = blockIdx.y * 32;
    int tx = threadIdx.x, ty = threadIdx.y;
#pragma unroll
    for (int r = 0; r < 4; r++)
        t[ty + 8 * r][tx] = W[(size_t)(k0 + ty + 8 * r) * N + n0 + tx];
    __syncthreads();
#pragma unroll
    for (int r = 0; r < 4; r++) {
        float v = t[tx][ty + 8 * r];
        __nv_bfloat16 h = __float2bfloat16_rn(v);
        __nv_bfloat16 l = __float2bfloat16_rn(v - __bfloat162float(h));
        size_t idx = (size_t)(n0 + ty + 8 * r) * K + k0 + tx;
        Thi[idx] = h;
        Tlo[idx] = l;
    }
}

// ---------------- embedding (+ split) ----------------
__global__ void embed_kernel(const int* __restrict__ idx,
                             const float* __restrict__ tok,
                             const float* __restrict__ pos,
                             float* __restrict__ x,
                             __nv_bfloat16* __restrict__ xhi,
                             __nv_bfloat16* __restrict__ xlo) {
    int t = blockIdx.x;
    int tpos = t & (TT - 1);
    int id = idx[t];
    const float4* te = (const float4*)(tok + (size_t)id * CC);
    const float4* pe = (const float4*)(pos + (size_t)tpos * CC);
    int c = threadIdx.x;
    float4 a = te[c], b = pe[c];
    float4 v = make_float4(a.x + b.x, a.y + b.y, a.z + b.z, a.w + b.w);
    ((float4*)(x + (size_t)t * CC))[c] = v;
    size_t off = (size_t)t * CC + c * 4;
    split_store(xhi, xlo, off,     make_float2(v.x, v.y));
    split_store(xhi, xlo, off + 2, make_float2(v.z, v.w));
}

// ---------------- launch ----------------
static inline void gemm_launch(int epi, const __nv_bfloat16* ahi, const __nv_bfloat16* alo,
                               const __nv_bfloat16* bhi, const __nv_bfloat16* blo,
                               float* c, __nv_bfloat16* hi, __nv_bfloat16* lo,
                               int M, int N, int K) {
    dim3 grid(M / 128, N / 128);
    if (epi == 0) mma_gemm<0><<<grid, 256, GEMM_SMEM>>>(ahi, alo, bhi, blo, c, hi, lo, M, N, K);
    if (epi == 1) mma_gemm<1><<<grid, 256, GEMM_SMEM>>>(ahi, alo, bhi, blo, c, hi, lo, M, N, K);
    if (epi == 2) mma_gemm<2><<<grid, 256, GEMM_SMEM>>>(ahi, alo, bhi, blo, c, hi, lo, M, N, K);
}

extern "C" void kernel_launch(void* const* d_in, const int* in_sizes, int n_in,
                              void* d_out, int out_size) {
    const int*   idx    = (const int*)d_in[0];
    const float* tok    = (const float*)d_in[1];
    const float* pos    = (const float*)d_in[2];
    const float* wk     = (const float*)d_in[3];
    const float* wq     = (const float*)d_in[4];
    const float* wv     = (const float*)d_in[5];
    const float* w_proj = (const float*)d_in[6];
    const float* w_in   = (const float*)d_in[7];
    const float* w_out  = (const float*)d_in[8];
    float* out = (float*)d_out;

    cudaFuncSetAttribute(mma_gemm<0>, cudaFuncAttributeMaxDynamicSharedMemorySize, GEMM_SMEM);
    cudaFuncSetAttribute(mma_gemm<1>, cudaFuncAttributeMaxDynamicSharedMemorySize, GEMM_SMEM);
    cudaFuncSetAttribute(mma_gemm<2>, cudaFuncAttributeMaxDynamicSharedMemorySize, GEMM_SMEM);
    cudaFuncSetAttribute(flash_attn,  cudaFuncAttributeMaxDynamicSharedMemorySize, FA_SMEM);

    float *x, *q, *k, *v;
    cudaGetSymbolAddress((void**)&x, g_x);
    cudaGetSymbolAddress((void**)&q, g_q);
    cudaGetSymbolAddress((void**)&k, g_k);
    cudaGetSymbolAddress((void**)&v, g_v);

    __nv_bfloat16 *xhi, *xlo, *ohi, *olo, *hhi, *hlo;
    cudaGetSymbolAddress((void**)&xhi, g_xhi); cudaGetSymbolAddress((void**)&xlo, g_xlo);
    cudaGetSymbolAddress((void**)&ohi, g_ohi); cudaGetSymbolAddress((void**)&olo, g_olo);
    cudaGetSymbolAddress((void**)&hhi, g_hhi); cudaGetSymbolAddress((void**)&hlo, g_hlo);

    __nv_bfloat16 *wk_hi, *wk_lo, *wq_hi, *wq_lo, *wv_hi, *wv_lo, *wp_hi, *wp_lo;
    __nv_bfloat16 *win_hi, *win_lo, *wout_hi, *wout_lo, *tok_hi, *tok_lo;
    cudaGetSymbolAddress((void**)&wk_hi, g_wk_hi);   cudaGetSymbolAddress((void**)&wk_lo, g_wk_lo);
    cudaGetSymbolAddress((void**)&wq_hi, g_wq_hi);   cudaGetSymbolAddress((void**)&wq_lo, g_wq_lo);
    cudaGetSymbolAddress((void**)&wv_hi, g_wv_hi);   cudaGetSymbolAddress((void**)&wv_lo, g_wv_lo);
    cudaGetSymbolAddress((void**)&wp_hi, g_wp_hi);   cudaGetSymbolAddress((void**)&wp_lo, g_wp_lo);
    cudaGetSymbolAddress((void**)&win_hi, g_win_hi); cudaGetSymbolAddress((void**)&win_lo, g_win_lo);
    cudaGetSymbolAddress((void**)&wout_hi, g_wout_hi); cudaGetSymbolAddress((void**)&wout_lo, g_wout_lo);
    cudaGetSymbolAddress((void**)&tok_hi, g_tok_hi); cudaGetSymbolAddress((void**)&tok_lo, g_tok_lo);

    const int M = BB * TT;  // 4096
    dim3 tb(32, 8);

    // ---- per-launch weight conversion ----
    tsplit_kernel<<<dim3(CC / 32, CC / 32), tb>>>(wk, wk_hi, wk_lo, CC, CC);
    tsplit_kernel<<<dim3(CC / 32, CC / 32), tb>>>(wq, wq_hi, wq_lo, CC, CC);
    tsplit_kernel<<<dim3(CC / 32, CC / 32), tb>>>(wv, wv_hi, wv_lo, CC, CC);
    split_kernel<<<(CC * CC / 4 + 255) / 256, 256>>>(w_proj, wp_hi, wp_lo, CC * CC / 4);
    tsplit_kernel<<<dim3(FF / 32, CC / 32), tb>>>(w_in, win_hi, win_lo, CC, FF);
    tsplit_kernel<<<dim3(CC / 32, FF / 32), tb>>>(w_out, wout_hi, wout_lo, FF, CC);
    split_kernel<<<((size_t)VV * CC / 4 + 255) / 256, 256>>>(tok, tok_hi, tok_lo, VV * CC / 4);

    embed_kernel<<<M, 256>>>(idx, tok, pos, x, xhi, xlo);

    for (int layer = 0; layer < NLAYER; ++layer) {
        // reference quirk: k <- wk, v <- wq, q <- wv
        gemm_launch(0, xhi, xlo, wk_hi, wk_lo, k, nullptr, nullptr, M, CC, CC);
        gemm_launch(0, xhi, xlo, wq_hi, wq_lo, v, nullptr, nullptr, M, CC, CC);
        gemm_launch(0, xhi, xlo, wv_hi, wv_lo, q, nullptr, nullptr, M, CC, CC);

        flash_attn<<<dim3(16, BB * HH), 256, FA_SMEM>>>(q, k, v, ohi, olo);

        // x += o @ w_proj^T ; split x
        gemm_launch(1, ohi, olo, wp_hi, wp_lo, x, xhi, xlo, M, CC, CC);

        // h = relu(x @ w_in) (split only) ; x += h @ w_out ; split x
        gemm_launch(2, xhi, xlo, win_hi, win_lo, x /*unused*/, hhi, hlo, M, FF, CC);
        gemm_launch(1, hhi, hlo, wout_hi, wout_lo, x, xhi, xlo, M, CC, FF);
    }

    // logits = x @ token_emb^T
    gemm_launch(0, xhi, xlo, tok_hi, tok_lo, out, nullptr, nullptr, M, VV, CC);
}

// round 6
// speedup vs baseline: 2.9184x; 1.1768x over previous
#include <cuda_runtime.h>
#include <cuda_bf16.h>
#include <cuda_fp16.h>
#include <cstdint>

#define BB 4
#define TT 1024
#define CC 1024
#define HH 16
#define HD 64
#define FF 4096
#define VV 32000
#define NLAYER 4

// ---------------- scratch (device globals) ----------------
__device__ float g_x[BB * TT * CC];

__device__ __nv_bfloat16 g_xhi[BB * TT * CC], g_xlo[BB * TT * CC];
__device__ __nv_bfloat16 g_ohi[BB * TT * CC], g_olo[BB * TT * CC];
__device__ __nv_bfloat16 g_hhi[BB * TT * FF], g_hlo[BB * TT * FF];

__device__ __half g_qkvh[BB * TT * 3 * CC], g_qkvl[BB * TT * 3 * CC];

__device__ __nv_bfloat16 g_wqkv_hi[3 * CC * CC], g_wqkv_lo[3 * CC * CC];
__device__ __nv_bfloat16 g_wp_hi[CC * CC], g_wp_lo[CC * CC];
__device__ __nv_bfloat16 g_win_hi[FF * CC], g_win_lo[FF * CC];
__device__ __nv_bfloat16 g_wout_hi[CC * FF], g_wout_lo[CC * FF];
__device__ __nv_bfloat16 g_tok_hi[(size_t)VV * CC], g_tok_lo[(size_t)VV * CC];

// ================= PTX helpers (baseline ISA sm_80+) =================
__device__ __forceinline__ uint32_t smem_to_u32(const void* p) {
    uint32_t a;
    asm("{ .reg .u64 t; cvta.to.shared.u64 t, %1; cvt.u32.u64 %0, t; }" : "=r"(a) : "l"(p));
    return a;
}
__device__ __forceinline__ void cpasync16(uint32_t dst, const void* src) {
    asm volatile("cp.async.cg.shared.global [%0], [%1], 16;" :: "r"(dst), "l"(src));
}
#define CP_COMMIT() asm volatile("cp.async.commit_group;" ::: "memory")
#define CP_WAIT0()  asm volatile("cp.async.wait_group 0;" ::: "memory")
#define CP_WAIT1()  asm volatile("cp.async.wait_group 1;" ::: "memory")

__device__ __forceinline__ void ldsm4(uint32_t* r, uint32_t addr) {
    asm volatile("ldmatrix.sync.aligned.m8n8.x4.shared.b16 {%0,%1,%2,%3}, [%4];"
                 : "=r"(r[0]), "=r"(r[1]), "=r"(r[2]), "=r"(r[3]) : "r"(addr));
}
__device__ __forceinline__ void ldsm4t(uint32_t* r, uint32_t addr) {
    asm volatile("ldmatrix.sync.aligned.m8n8.x4.trans.shared.b16 {%0,%1,%2,%3}, [%4];"
                 : "=r"(r[0]), "=r"(r[1]), "=r"(r[2]), "=r"(r[3]) : "r"(addr));
}
__device__ __forceinline__ void mma16816(float* d, const uint32_t* a, uint32_t b0, uint32_t b1) {
    asm volatile(
        "mma.sync.aligned.m16n8k16.row.col.f32.bf16.bf16.f32 "
        "{%0,%1,%2,%3}, {%4,%5,%6,%7}, {%8,%9}, {%0,%1,%2,%3};"
        : "+f"(d[0]), "+f"(d[1]), "+f"(d[2]), "+f"(d[3])
        : "r"(a[0]), "r"(a[1]), "r"(a[2]), "r"(a[3]), "r"(b0), "r"(b1));
}
__device__ __forceinline__ void mma16816h(float* d, const uint32_t* a, uint32_t b0, uint32_t b1) {
    asm volatile(
        "mma.sync.aligned.m16n8k16.row.col.f32.f16.f16.f32 "
        "{%0,%1,%2,%3}, {%4,%5,%6,%7}, {%8,%9}, {%0,%1,%2,%3};"
        : "+f"(d[0]), "+f"(d[1]), "+f"(d[2]), "+f"(d[3])
        : "r"(a[0]), "r"(a[1]), "r"(a[2]), "r"(a[3]), "r"(b0), "r"(b1));
}

__device__ __forceinline__ void split_store(__nv_bfloat16* __restrict__ hi,
                                            __nv_bfloat16* __restrict__ lo,
                                            size_t off, float2 v) {
    __nv_bfloat16 h0 = __float2bfloat16_rn(v.x);
    __nv_bfloat16 h1 = __float2bfloat16_rn(v.y);
    __nv_bfloat16 l0 = __float2bfloat16_rn(v.x - __bfloat162float(h0));
    __nv_bfloat16 l1 = __float2bfloat16_rn(v.y - __bfloat162float(h1));
    *(__nv_bfloat162*)(hi + off) = __nv_bfloat162(h0, h1);
    *(__nv_bfloat162*)(lo + off) = __nv_bfloat162(l0, l1);
}
__device__ __forceinline__ void hsplit_store(__half* __restrict__ hi, __half* __restrict__ lo,
                                             size_t off, float2 v) {
    __half h0 = __float2half_rn(v.x);
    __half h1 = __float2half_rn(v.y);
    __half l0 = __float2half_rn(v.x - __half2float(h0));
    __half l1 = __float2half_rn(v.y - __half2float(h1));
    *(__half2*)(hi + off) = __halves2half2(h0, h1);
    *(__half2*)(lo + off) = __halves2half2(l0, l1);
}
__device__ __forceinline__ uint32_t packh2(float a, float b) {
    __half2 h = __floats2half2_rn(a, b);
    return *reinterpret_cast<uint32_t*>(&h);
}

// ================= split-bf16 HMMA GEMM =================
// D[M,N] = Ahi/lo[M,K] @ (Bhi/lo[N,K])^T, fp32 acc.
// EPI 0: C = D;  EPI 1: C += D, split(C)->Hi/Lo;  EPI 2: split(relu(D))->Hi/Lo;
// EPI 3: fp16-split(D) -> Fh/Fl.
#define KC 64
#define TILE_BYTES 16384
#define STAGE_BYTES (4 * TILE_BYTES)
#define GEMM_SMEM (2 * STAGE_BYTES)   // 128 KB

__device__ __forceinline__ uint32_t swz(uint32_t off) { return off ^ ((off >> 3) & 0x70); }

__device__ __forceinline__ void load_tile_async(const __nv_bfloat16* __restrict__ src,
                                                size_t row0, int K, int k0,
                                                uint32_t dst_base, int tid) {
#pragma unroll
    for (int l = 0; l < 4; l++) {
        int seg = tid + l * 256;
        int row = seg >> 3;
        int c16 = seg & 7;
        uint32_t off = (uint32_t)(row * 128 + c16 * 16);
        cpasync16(dst_base + swz(off), src + (row0 + row) * (size_t)K + k0 + c16 * 8);
    }
}

template <int EPI>
__global__ __launch_bounds__(256, 1)
void mma_gemm(const __nv_bfloat16* __restrict__ Ahi, const __nv_bfloat16* __restrict__ Alo,
              const __nv_bfloat16* __restrict__ Bhi, const __nv_bfloat16* __restrict__ Blo,
              float* __restrict__ C, __nv_bfloat16* __restrict__ Hi,
              __nv_bfloat16* __restrict__ Lo, __half* __restrict__ Fh,
              __half* __restrict__ Fl, int M, int N, int K) {
    extern __shared__ __align__(1024) char smem[];
    uint32_t sbase = smem_to_u32(smem);
    int tid = threadIdx.x;
    int wid = tid >> 5, lane = tid & 31;
    int bm = blockIdx.x, bn = blockIdx.y;
    size_t arow0 = (size_t)bm * 128, brow0 = (size_t)bn * 128;

    int wm = wid & 3, wn = wid >> 2;
    int m0 = wm * 32, n0 = wn * 64;

    float acc[2][8][4];
#pragma unroll
    for (int i = 0; i < 2; i++)
#pragma unroll
        for (int j = 0; j < 8; j++)
#pragma unroll
            for (int r = 0; r < 4; r++) acc[i][j][r] = 0.f;

    const int nch = K / KC;
    {
        uint32_t st = sbase;
        load_tile_async(Ahi, arow0, K, 0, st, tid);
        load_tile_async(Alo, arow0, K, 0, st + TILE_BYTES, tid);
        load_tile_async(Bhi, brow0, K, 0, st + 2 * TILE_BYTES, tid);
        load_tile_async(Blo, brow0, K, 0, st + 3 * TILE_BYTES, tid);
        CP_COMMIT();
    }

    for (int c = 0; c < nch; ++c) {
        int s = c & 1;
        CP_WAIT0();
        __syncthreads();
        if (c + 1 < nch) {
            uint32_t st = sbase + (s ^ 1) * STAGE_BYTES;
            int k0 = (c + 1) * KC;
            load_tile_async(Ahi, arow0, K, k0, st, tid);
            load_tile_async(Alo, arow0, K, k0, st + TILE_BYTES, tid);
            load_tile_async(Bhi, brow0, K, k0, st + 2 * TILE_BYTES, tid);
            load_tile_async(Blo, brow0, K, k0, st + 3 * TILE_BYTES, tid);
            CP_COMMIT();
        }
        uint32_t stb = sbase + s * STAGE_BYTES;

#pragma unroll
        for (int j = 0; j < 4; j++) {
            uint32_t ah[2][4], al[2][4], bh[4][4], bl[4][4];
            int lr = lane & 15, lc = (lane >> 4) * 16;
#pragma unroll
            for (int mt = 0; mt < 2; mt++) {
                uint32_t off = swz((uint32_t)((m0 + mt * 16 + lr) * 128 + j * 32 + lc));
                ldsm4(ah[mt], stb + off);
                ldsm4(al[mt], stb + TILE_BYTES + off);
            }
#pragma unroll
            for (int ng = 0; ng < 4; ng++) {
                uint32_t off = swz((uint32_t)((n0 + ng * 16 + lr) * 128 + j * 32 + lc));
                ldsm4(bh[ng], stb + 2 * TILE_BYTES + off);
                ldsm4(bl[ng], stb + 3 * TILE_BYTES + off);
            }
#pragma unroll
            for (int mt = 0; mt < 2; mt++) {
#pragma unroll
                for (int ng = 0; ng < 4; ng++) {
                    mma16816(acc[mt][2 * ng],     ah[mt], bh[ng][0], bh[ng][2]);
                    mma16816(acc[mt][2 * ng + 1], ah[mt], bh[ng][1], bh[ng][3]);
                    mma16816(acc[mt][2 * ng],     ah[mt], bl[ng][0], bl[ng][2]);
                    mma16816(acc[mt][2 * ng + 1], ah[mt], bl[ng][1], bl[ng][3]);
                    mma16816(acc[mt][2 * ng],     al[mt], bh[ng][0], bh[ng][2]);
                    mma16816(acc[mt][2 * ng + 1], al[mt], bh[ng][1], bh[ng][3]);
                }
            }
        }
    }

    int r = lane >> 2, cp = (lane & 3) * 2;
#pragma unroll
    for (int mt = 0; mt < 2; mt++) {
        int grow = bm * 128 + m0 + mt * 16 + r;
#pragma unroll
        for (int t = 0; t < 8; t++) {
            int gcol = bn * 128 + n0 + t * 8 + cp;
            size_t o0 = (size_t)grow * N + gcol;
            size_t o1 = (size_t)(grow + 8) * N + gcol;
            float2 v0 = make_float2(acc[mt][t][0], acc[mt][t][1]);
            float2 v1 = make_float2(acc[mt][t][2], acc[mt][t][3]);
            if (EPI == 0) {
                *(float2*)(C + o0) = v0;
                *(float2*)(C + o1) = v1;
            }
            if (EPI == 1) {
                float2 c0 = *(const float2*)(C + o0);
                float2 c1 = *(const float2*)(C + o1);
                v0.x += c0.x; v0.y += c0.y;
                v1.x += c1.x; v1.y += c1.y;
                *(float2*)(C + o0) = v0;
                *(float2*)(C + o1) = v1;
                split_store(Hi, Lo, o0, v0);
                split_store(Hi, Lo, o1, v1);
            }
            if (EPI == 2) {
                v0.x = fmaxf(v0.x, 0.f); v0.y = fmaxf(v0.y, 0.f);
                v1.x = fmaxf(v1.x, 0.f); v1.y = fmaxf(v1.y, 0.f);
                split_store(Hi, Lo, o0, v0);
                split_store(Hi, Lo, o1, v1);
            }
            if (EPI == 3) {
                hsplit_store(Fh, Fl, o0, v0);
                hsplit_store(Fh, Fl, o1, v1);
            }
        }
    }
}

// ================= flash attention (fp16 HMMA) =================
// qkv packed [M][3072]: cols 0-1023 = K, 1024-2047 = V, 2048-3071 = Q.
// grid (16, BB*HH), 128 threads (4 warps; warp owns 16 q-rows of the 64-row tile).
#define FH_STAGE 24576                   // K(8K) + Vh(8K) + Vl(8K)
#define FH_SMEM  (8192 + 2 * FH_STAGE)   // Q + 2 stages = 57344

__device__ __forceinline__ void load_tile_h(const __half* __restrict__ src,
                                            uint32_t dst, int tid) {
#pragma unroll
    for (int l = 0; l < 4; l++) {
        int seg = tid + l * 128;
        int row = seg >> 3, c16 = seg & 7;
        uint32_t off = (uint32_t)(row * 128 + c16 * 16);
        cpasync16(dst + swz(off), src + (size_t)row * 3072 + c16 * 8);
    }
}

__global__ __launch_bounds__(128)
void flash_attn_h(const __half* __restrict__ qkvh, const __half* __restrict__ qkvl,
                  __nv_bfloat16* __restrict__ ohi, __nv_bfloat16* __restrict__ olo) {
    extern __shared__ __align__(1024) char fsm[];
    uint32_t sb = smem_to_u32(fsm);
    const uint32_t Qs = sb;
    int ti = 15 - (int)blockIdx.x;
    int z = blockIdx.y;
    int b = z >> 4, h = z & 15;
    int tid = threadIdx.x, lane = tid & 31, w = tid >> 5;
    const unsigned FM = 0xffffffffu;

    const size_t rowbase = (size_t)b * TT;
    const __half* qptr = qkvh + (rowbase + ti * 64) * 3072 + 2048 + h * 64;

    // prologue: Q + KV(0) in one commit group
    load_tile_h(qptr, Qs, tid);
    {
        const __half* kp = qkvh + rowbase * 3072 + h * 64;
        const __half* vhp = qkvh + rowbase * 3072 + 1024 + h * 64;
        const __half* vlp = qkvl + rowbase * 3072 + 1024 + h * 64;
        uint32_t st = sb + 8192;
        load_tile_h(kp, st, tid);
        load_tile_h(vhp, st + 8192, tid);
        load_tile_h(vlp, st + 16384, tid);
    }
    CP_COMMIT();

    float od[8][4];
#pragma unroll
    for (int t = 0; t < 8; t++)
#pragma unroll
        for (int r = 0; r < 4; r++) od[t][r] = 0.f;
    float m[2] = {-1e30f, -1e30f}, l[2] = {0.f, 0.f};

    for (int tj = 0; tj <= ti; ++tj) {
        int s = tj & 1;
        if (tj < ti) {
            size_t jr = rowbase + (size_t)(tj + 1) * 64;
            uint32_t st = sb + 8192 + (s ^ 1) * FH_STAGE;
            load_tile_h(qkvh + jr * 3072 + h * 64, st, tid);
            load_tile_h(qkvh + jr * 3072 + 1024 + h * 64, st + 8192, tid);
            load_tile_h(qkvl + jr * 3072 + 1024 + h * 64, st + 16384, tid);
            CP_COMMIT();
            CP_WAIT1();
        } else {
            CP_WAIT0();
        }
        __syncthreads();

        uint32_t Ks = sb + 8192 + s * FH_STAGE;
        uint32_t Vh = Ks + 8192, Vl = Ks + 16384;

        // ---- S = Q K^T ----
        float sf[8][4];
#pragma unroll
        for (int t = 0; t < 8; t++)
#pragma unroll
            for (int r = 0; r < 4; r++) sf[t][r] = 0.f;

        int lr = lane & 15, lc = (lane >> 4) * 16;
#pragma unroll
        for (int ks = 0; ks < 4; ks++) {
            uint32_t aq[4];
            ldsm4(aq, Qs + swz((uint32_t)((w * 16 + lr) * 128 + ks * 32 + lc)));
#pragma unroll
            for (int g = 0; g < 4; g++) {
                uint32_t bk[4];
                ldsm4(bk, Ks + swz((uint32_t)((g * 16 + lr) * 128 + ks * 32 + lc)));
                mma16816h(sf[2 * g],     aq, bk[0], bk[2]);
                mma16816h(sf[2 * g + 1], aq, bk[1], bk[3]);
            }
        }

        // scale + causal mask
#pragma unroll
        for (int t = 0; t < 8; t++)
#pragma unroll
            for (int r = 0; r < 4; r++) sf[t][r] *= 0.125f;
        if (tj == ti) {
            int colb = (lane & 3) * 2;
            int row0 = w * 16 + (lane >> 2);
#pragma unroll
            for (int t = 0; t < 8; t++) {
                int c0 = t * 8 + colb;
                if (c0 > row0)     sf[t][0] = -1e30f;
                if (c0 + 1 > row0) sf[t][1] = -1e30f;
                if (c0 > row0 + 8)     sf[t][2] = -1e30f;
                if (c0 + 1 > row0 + 8) sf[t][3] = -1e30f;
            }
        }

        // ---- online softmax (rows split: regs {0,1} row r, {2,3} row r+8) ----
        float fscale[2];
#pragma unroll
        for (int hh = 0; hh < 2; hh++) {
            float tm = -1e30f;
#pragma unroll
            for (int t = 0; t < 8; t++)
                tm = fmaxf(tm, fmaxf(sf[t][2 * hh], sf[t][2 * hh + 1]));
            tm = fmaxf(tm, __shfl_xor_sync(FM, tm, 1));
            tm = fmaxf(tm, __shfl_xor_sync(FM, tm, 2));
            float mn = fmaxf(m[hh], tm);
            float f = __expf(m[hh] - mn);
            m[hh] = mn; fscale[hh] = f;
            float ps = 0.f;
#pragma unroll
            for (int t = 0; t < 8; t++) {
                float p0 = __expf(sf[t][2 * hh] - mn);
                float p1 = __expf(sf[t][2 * hh + 1] - mn);
                sf[t][2 * hh] = p0; sf[t][2 * hh + 1] = p1;
                ps += p0 + p1;
            }
            ps += __shfl_xor_sync(FM, ps, 1);
            ps += __shfl_xor_sync(FM, ps, 2);
            l[hh] = l[hh] * f + ps;
        }
#pragma unroll
        for (int t = 0; t < 8; t++) {
            od[t][0] *= fscale[0]; od[t][1] *= fscale[0];
            od[t][2] *= fscale[1]; od[t][3] *= fscale[1];
        }

        // ---- pack P into fp16 A frags ----
        uint32_t aP[4][4];
#pragma unroll
        for (int ks = 0; ks < 4; ks++) {
            aP[ks][0] = packh2(sf[2 * ks][0], sf[2 * ks][1]);
            aP[ks][1] = packh2(sf[2 * ks][2], sf[2 * ks][3]);
            aP[ks][2] = packh2(sf[2 * ks + 1][0], sf[2 * ks + 1][1]);
            aP[ks][3] = packh2(sf[2 * ks + 1][2], sf[2 * ks + 1][3]);
        }

        // ---- o += P (Vh + Vl): B frags from ldmatrix.trans on V[j][d] ----
#pragma unroll
        for (int ks = 0; ks < 4; ks++) {
#pragma unroll
            for (int dg = 0; dg < 4; dg++) {
                uint32_t off = swz((uint32_t)((ks * 16 + lr) * 128 + dg * 32 + lc));
                uint32_t bv[4];
                ldsm4t(bv, Vh + off);
                mma16816h(od[2 * dg],     aP[ks], bv[0], bv[1]);
                mma16816h(od[2 * dg + 1], aP[ks], bv[2], bv[3]);
                ldsm4t(bv, Vl + off);
                mma16816h(od[2 * dg],     aP[ks], bv[0], bv[1]);
                mma16816h(od[2 * dg + 1], aP[ks], bv[2], bv[3]);
            }
        }
        __syncthreads();
    }

    // ---- epilogue: o / l -> split bf16 ----
    float inv0 = 1.f / l[0], inv1 = 1.f / l[1];
    size_t grow = rowbase + ti * 64 + w * 16 + (lane >> 2);
#pragma unroll
    for (int t = 0; t < 8; t++) {
        size_t off = grow * CC + h * 64 + t * 8 + (lane & 3) * 2;
        split_store(ohi, olo, off, make_float2(od[t][0] * inv0, od[t][1] * inv0));
        split_store(ohi, olo, off + (size_t)8 * CC,
                    make_float2(od[t][2] * inv1, od[t][3] * inv1));
    }
}

// ================= conversions =================
__global__ __launch_bounds__(256)
void split_kernel(const float* __restrict__ X, __nv_bfloat16* __restrict__ hi,
                  __nv_bfloat16* __restrict__ lo, int n4) {
    int i = blockIdx.x * 256 + threadIdx.x;
    if (i >= n4) return;
    float4 v = ((const float4*)X)[i];
    split_store(hi, lo, (size_t)i * 4,     make_float2(v.x, v.y));
    split_store(hi, lo, (size_t)i * 4 + 2, make_float2(v.z, v.w));
}

// W[K][N] fp32 -> T_hi/lo[N][K] bf16. block (32,8), grid (N/32, K/32)
__global__ __launch_bounds__(256)
void tsplit_kernel(const float* __restrict__ W, __nv_bfloat16* __restrict__ Thi,
                   __nv_bfloat16* __restrict__ Tlo, int K, int N) {
    __shared__ float t[32][33];
    int n0 = blockIdx.x * 32, k0 = blockIdx.y * 32;
    int tx = threadIdx.x, ty = threadIdx.y;
#pragma unroll
    for (int r = 0; r < 4; r++)
        t[ty + 8 * r][tx] = W[(size_t)(k0 + ty + 8 * r) * N + n0 + tx];
    __syncthreads();
#pragma unroll
    for (int r = 0; r < 4; r++) {
        float v = t[tx][ty + 8 * r];
        __nv_bfloat16 hh = __float2bfloat16_rn(v);
        __nv_bfloat16 ll = __float2bfloat16_rn(v - __bfloat162float(hh));
        size_t idx = (size_t)(n0 + ty + 8 * r) * K + k0 + tx;
        Thi[idx] = hh;
        Tlo[idx] = ll;
    }
}

// ---------------- embedding (+ split) ----------------
__global__ void embed_kernel(const int* __restrict__ idx,
                             const float* __restrict__ tok,
                             const float* __restrict__ pos,
                             float* __restrict__ x,
                             __nv_bfloat16* __restrict__ xhi,
                             __nv_bfloat16* __restrict__ xlo) {
    int t = blockIdx.x;
    int tpos = t & (TT - 1);
    int id = idx[t];
    const float4* te = (const float4*)(tok + (size_t)id * CC);
    const float4* pe = (const float4*)(pos + (size_t)tpos * CC);
    int c = threadIdx.x;
    float4 a = te[c], b = pe[c];
    float4 v = make_float4(a.x + b.x, a.y + b.y, a.z + b.z, a.w + b.w);
    ((float4*)(x + (size_t)t * CC))[c] = v;
    size_t off = (size_t)t * CC + c * 4;
    split_store(xhi, xlo, off,     make_float2(v.x, v.y));
    split_store(xhi, xlo, off + 2, make_float2(v.z, v.w));
}

// ---------------- launch ----------------
static inline void gemm_launch(int epi, const __nv_bfloat16* ahi, const __nv_bfloat16* alo,
                               const __nv_bfloat16* bhi, const __nv_bfloat16* blo,
                               float* c, __nv_bfloat16* hi, __nv_bfloat16* lo,
                               __half* fh, __half* fl, int M, int N, int K) {
    dim3 grid(M / 128, N / 128);
    if (epi == 0) mma_gemm<0><<<grid, 256, GEMM_SMEM>>>(ahi, alo, bhi, blo, c, hi, lo, fh, fl, M, N, K);
    if (epi == 1) mma_gemm<1><<<grid, 256, GEMM_SMEM>>>(ahi, alo, bhi, blo, c, hi, lo, fh, fl, M, N, K);
    if (epi == 2) mma_gemm<2><<<grid, 256, GEMM_SMEM>>>(ahi, alo, bhi, blo, c, hi, lo, fh, fl, M, N, K);
    if (epi == 3) mma_gemm<3><<<grid, 256, GEMM_SMEM>>>(ahi, alo, bhi, blo, c, hi, lo, fh, fl, M, N, K);
}

extern "C" void kernel_launch(void* const* d_in, const int* in_sizes, int n_in,
                              void* d_out, int out_size) {
    const int*   idx    = (const int*)d_in[0];
    const float* tok    = (const float*)d_in[1];
    const float* pos    = (const float*)d_in[2];
    const float* wk     = (const float*)d_in[3];
    const float* wq     = (const float*)d_in[4];
    const float* wv     = (const float*)d_in[5];
    const float* w_proj = (const float*)d_in[6];
    const float* w_in   = (const float*)d_in[7];
    const float* w_out  = (const float*)d_in[8];
    float* out = (float*)d_out;

    cudaFuncSetAttribute(mma_gemm<0>, cudaFuncAttributeMaxDynamicSharedMemorySize, GEMM_SMEM);
    cudaFuncSetAttribute(mma_gemm<1>, cudaFuncAttributeMaxDynamicSharedMemorySize, GEMM_SMEM);
    cudaFuncSetAttribute(mma_gemm<2>, cudaFuncAttributeMaxDynamicSharedMemorySize, GEMM_SMEM);
    cudaFuncSetAttribute(mma_gemm<3>, cudaFuncAttributeMaxDynamicSharedMemorySize, GEMM_SMEM);
    cudaFuncSetAttribute(flash_attn_h, cudaFuncAttributeMaxDynamicSharedMemorySize, FH_SMEM);

    float* x;
    cudaGetSymbolAddress((void**)&x, g_x);
    __nv_bfloat16 *xhi, *xlo, *ohi, *olo, *hhi, *hlo;
    cudaGetSymbolAddress((void**)&xhi, g_xhi); cudaGetSymbolAddress((void**)&xlo, g_xlo);
    cudaGetSymbolAddress((void**)&ohi, g_ohi); cudaGetSymbolAddress((void**)&olo, g_olo);
    cudaGetSymbolAddress((void**)&hhi, g_hhi); cudaGetSymbolAddress((void**)&hlo, g_hlo);
    __half *qkvh, *qkvl;
    cudaGetSymbolAddress((void**)&qkvh, g_qkvh); cudaGetSymbolAddress((void**)&qkvl, g_qkvl);

    __nv_bfloat16 *wqkv_hi, *wqkv_lo, *wp_hi, *wp_lo;
    __nv_bfloat16 *win_hi, *win_lo, *wout_hi, *wout_lo, *tok_hi, *tok_lo;
    cudaGetSymbolAddress((void**)&wqkv_hi, g_wqkv_hi); cudaGetSymbolAddress((void**)&wqkv_lo, g_wqkv_lo);
    cudaGetSymbolAddress((void**)&wp_hi, g_wp_hi);     cudaGetSymbolAddress((void**)&wp_lo, g_wp_lo);
    cudaGetSymbolAddress((void**)&win_hi, g_win_hi);   cudaGetSymbolAddress((void**)&win_lo, g_win_lo);
    cudaGetSymbolAddress((void**)&wout_hi, g_wout_hi); cudaGetSymbolAddress((void**)&wout_lo, g_wout_lo);
    cudaGetSymbolAddress((void**)&tok_hi, g_tok_hi);   cudaGetSymbolAddress((void**)&tok_lo, g_tok_lo);

    const int M = BB * TT;  // 4096
    dim3 tb(32, 8);

    // Layer 1 interleaved with conversions (keeps launch #5 = QKV mma_gemm for ncu -s 5)
    embed_kernel<<<M, 256>>>(idx, tok, pos, x, xhi, xlo);                               // 0
    // reference quirk: k <- wk, v <- wq, q <- wv  (pack rows: K=0..1023, V=1024.., Q=2048..)
    tsplit_kernel<<<dim3(CC / 32, CC / 32), tb>>>(wk, wqkv_hi, wqkv_lo, CC, CC);        // 1
    tsplit_kernel<<<dim3(CC / 32, CC / 32), tb>>>(wq, wqkv_hi + 1024 * CC, wqkv_lo + 1024 * CC, CC, CC); // 2
    tsplit_kernel<<<dim3(CC / 32, CC / 32), tb>>>(wv, wqkv_hi + 2048 * CC, wqkv_lo + 2048 * CC, CC, CC); // 3
    split_kernel<<<(CC * CC / 4 + 255) / 256, 256>>>(w_proj, wp_hi, wp_lo, CC * CC / 4); // 4

    for (int layer = 0; layer < NLAYER; ++layer) {
        gemm_launch(3, xhi, xlo, wqkv_hi, wqkv_lo, nullptr, nullptr, nullptr,
                    qkvh, qkvl, M, 3 * CC, CC);                                          // 5 on layer 0
        flash_attn_h<<<dim3(16, BB * HH), 128, FH_SMEM>>>(qkvh, qkvl, ohi, olo);

        // x += o @ w_proj^T ; split x
        gemm_launch(1, ohi, olo, wp_hi, wp_lo, x, xhi, xlo, nullptr, nullptr, M, CC, CC);

        if (layer == 0) {
            tsplit_kernel<<<dim3(FF / 32, CC / 32), tb>>>(w_in, win_hi, win_lo, CC, FF);
        }
        // h = relu(x @ w_in) (split only)
        gemm_launch(2, xhi, xlo, win_hi, win_lo, nullptr, hhi, hlo, nullptr, nullptr, M, FF, CC);
        if (layer == 0) {
            tsplit_kernel<<<dim3(CC / 32, FF / 32), tb>>>(w_out, wout_hi, wout_lo, FF, CC);
        }
        // x += h @ w_out ; split x
        gemm_launch(1, hhi, hlo, wout_hi, wout_lo, x, xhi, xlo, nullptr, nullptr, M, CC, FF);
    }

    // logits = x @ token_emb^T
    split_kernel<<<((size_t)VV * CC / 4 + 255) / 256, 256>>>(tok, tok_hi, tok_lo, VV * CC / 4);
    gemm_launch(0, xhi, xlo, tok_hi, tok_lo, out, nullptr, nullptr, nullptr, nullptr, M, VV, CC);
}